// round 16
// baseline (speedup 1.0000x reference)
#include <cuda_runtime.h>
#include <cuda_fp16.h>
#include <math.h>
#include <stdint.h>

#define BATCH 8
#define SEQ   2048
#define EMB   1024
#define DH    64
#define NROWS (BATCH * SEQ)   // 16384
#define NKT   (SEQ / 64)      // 32 k-tiles

// Pre-split fp16 operands produced by the QKV kernel.
__device__ __half g_Qhi[NROWS * DH];
__device__ __half g_Qlo[NROWS * DH];
__device__ __half g_Khi[NROWS * DH];
__device__ __half g_VThi[BATCH * DH * SEQ];  // [b][d][s]
__device__ __half g_WhiT[192 * EMB];          // [n][k]

// ---------------------------------------------------------------------------
// helpers
// ---------------------------------------------------------------------------
__device__ __forceinline__ void mma_f16(float* c, const uint32_t* a, const uint32_t* b) {
    asm volatile(
        "mma.sync.aligned.m16n8k16.row.col.f32.f16.f16.f32 "
        "{%0,%1,%2,%3}, {%4,%5,%6,%7}, {%8,%9}, {%0,%1,%2,%3};"
        : "+f"(c[0]), "+f"(c[1]), "+f"(c[2]), "+f"(c[3])
        : "r"(a[0]), "r"(a[1]), "r"(a[2]), "r"(a[3]), "r"(b[0]), "r"(b[1]));
}

__device__ __forceinline__ void ldsm4(uint32_t* r, uint32_t a) {
    asm volatile("ldmatrix.sync.aligned.m8n8.x4.shared.b16 {%0,%1,%2,%3}, [%4];"
        : "=r"(r[0]), "=r"(r[1]), "=r"(r[2]), "=r"(r[3]) : "r"(a));
}

__device__ __forceinline__ uint32_t smem_u32(const void* p) {
    uint32_t a;
    asm("{ .reg .u64 t; cvta.to.shared.u64 t, %1; cvt.u32.u64 %0, t; }"
        : "=r"(a) : "l"(p));
    return a;
}

__device__ __forceinline__ void cp16(uint32_t dst, const void* src) {
    asm volatile("cp.async.cg.shared.global [%0], [%1], 16;" :: "r"(dst), "l"(src));
}
#define CP_COMMIT() asm volatile("cp.async.commit_group;" ::: "memory")

// Fast 2^t on the FMA pipe (abs err ~2.4e-6 for |t| <= ~12).
__device__ __forceinline__ float fexp2(float t) {
    float z = t + 12582912.0f;
    float f = t - (z - 12582912.0f);
    int   e = __float_as_int(z) << 23;
    float p = 0.0013333558f;
    p = fmaf(p, f, 0.0096181291f);
    p = fmaf(p, f, 0.0555041087f);
    p = fmaf(p, f, 0.2402265070f);
    p = fmaf(p, f, 0.6931471806f);
    p = fmaf(p, f, 1.0f);
    return __int_as_float(__float_as_int(p) + e);
}

__device__ __forceinline__ uint32_t hpack_hi(float a, float b) {
    __half2 h = __floats2half2_rn(a, b);
    return *(uint32_t*)&h;
}
__device__ __forceinline__ uint32_t hpack_lo(float a, float b) {
    __half ha = __float2half_rn(a), hb = __float2half_rn(b);
    __half2 l = __halves2half2(__float2half_rn(a - __half2float(ha)),
                               __float2half_rn(b - __half2float(hb)));
    return *(uint32_t*)&l;
}

// ---------------------------------------------------------------------------
// Kernel 0: W [1024,192] fp32 -> transposed hi fp16 [192][1024]
// ---------------------------------------------------------------------------
__global__ void wconv_kernel(const float* __restrict__ W) {
    int idx = blockIdx.x * 256 + threadIdx.x;
    int k = idx & 1023;
    int n = idx >> 10;
    g_WhiT[(size_t)n * EMB + k] = __float2half_rn(W[(size_t)k * 192 + n]);
}

// ---------------------------------------------------------------------------
// Kernel 1: QKV projection (mma.sync, x split hi/lo, W hi only: 2-term).
// Emits split Q (hi/lo), hi K, and transposed VT-hi (via smem staging).
// (Byte-identical to the 180.2us R12 version.)
// ---------------------------------------------------------------------------
#define ASTR 40
#define QSM_AHI 0
#define QSM_ALO 5120
#define QSM_BHI 10240
#define QSM_TOT 25600

__global__ __launch_bounds__(256) void qkv_mma_kernel(
    const float* __restrict__ x,
    const float* __restrict__ bias)
{
    __shared__ char qsm[QSM_TOT];
    __half* sAhi = (__half*)(qsm + QSM_AHI);
    __half* sAlo = (__half*)(qsm + QSM_ALO);
    __half* sBhi = (__half*)(qsm + QSM_BHI);

    const int tid = threadIdx.x;
    const int lid = tid & 31;
    const int wid = tid >> 5;
    const int g   = lid >> 2;
    const int tig = lid & 3;
    const int warp_m = wid & 3;
    const int warp_n = wid >> 2;
    const int m0 = blockIdx.x * 64;

    float acc[12][4];
    #pragma unroll
    for (int j = 0; j < 12; j++)
        #pragma unroll
        for (int i = 0; i < 4; i++) acc[j][i] = 0.0f;

    for (int k0 = 0; k0 < EMB; k0 += 32) {
        __syncthreads();
        #pragma unroll
        for (int u = 0; u < 2; u++) {
            int id  = tid + u * 256;
            int row = id >> 3;
            int c4  = id & 7;
            float4 v = *(const float4*)&x[(size_t)(m0 + row) * EMB + k0 + c4 * 4];
            int e = row * ASTR + c4 * 4;
            *(uint32_t*)&sAhi[e]     = hpack_hi(v.x, v.y);
            *(uint32_t*)&sAhi[e + 2] = hpack_hi(v.z, v.w);
            *(uint32_t*)&sAlo[e]     = hpack_lo(v.x, v.y);
            *(uint32_t*)&sAlo[e + 2] = hpack_lo(v.z, v.w);
        }
        #pragma unroll
        for (int u = 0; u < 6; u++) {
            int id  = tid + u * 256;
            int row = id >> 3;
            int c   = id & 7;
            uint2 vh = *(const uint2*)&g_WhiT[(size_t)row * EMB + k0 + c * 4];
            *(uint2*)&sBhi[row * ASTR + c * 4] = vh;
        }
        __syncthreads();

        #pragma unroll
        for (int ks = 0; ks < 2; ks++) {
            const int kb = ks * 16;
            const int ra = warp_m * 16 + g;
            uint32_t ah[4], al[4];
            ah[0] = *(const uint32_t*)&sAhi[ra * ASTR + kb + 2 * tig];
            ah[1] = *(const uint32_t*)&sAhi[(ra + 8) * ASTR + kb + 2 * tig];
            ah[2] = *(const uint32_t*)&sAhi[ra * ASTR + kb + 8 + 2 * tig];
            ah[3] = *(const uint32_t*)&sAhi[(ra + 8) * ASTR + kb + 8 + 2 * tig];
            al[0] = *(const uint32_t*)&sAlo[ra * ASTR + kb + 2 * tig];
            al[1] = *(const uint32_t*)&sAlo[(ra + 8) * ASTR + kb + 2 * tig];
            al[2] = *(const uint32_t*)&sAlo[ra * ASTR + kb + 8 + 2 * tig];
            al[3] = *(const uint32_t*)&sAlo[(ra + 8) * ASTR + kb + 8 + 2 * tig];

            #pragma unroll
            for (int j = 0; j < 12; j++) {
                const int nb = warp_n * 96 + j * 8 + g;
                uint32_t bh[2];
                bh[0] = *(const uint32_t*)&sBhi[nb * ASTR + kb + 2 * tig];
                bh[1] = *(const uint32_t*)&sBhi[nb * ASTR + kb + 8 + 2 * tig];
                mma_f16(acc[j], ah, bh);
                mma_f16(acc[j], al, bh);
            }
        }
    }

    __syncthreads();   // done with A/B tiles; reuse smem for V staging
    float* sV = (float*)qsm;       // [64][68] fp32 = 17408 B
    const int row_l = warp_m * 16 + g;

    #pragma unroll
    for (int j = 0; j < 12; j++) {
        int nglob = warp_n * 96 + j * 8 + 2 * tig;
        float b0 = bias[nglob], b1 = bias[nglob + 1];
        float v0 = acc[j][0] + b0, v1 = acc[j][1] + b1;
        float v2 = acc[j][2] + b0, v3 = acc[j][3] + b1;
        if (nglob < 64) {
            size_t r0 = (size_t)(m0 + row_l) * DH + nglob;
            size_t r1 = (size_t)(m0 + row_l + 8) * DH + nglob;
            *(uint32_t*)&g_Qhi[r0] = hpack_hi(v0, v1);
            *(uint32_t*)&g_Qlo[r0] = hpack_lo(v0, v1);
            *(uint32_t*)&g_Qhi[r1] = hpack_hi(v2, v3);
            *(uint32_t*)&g_Qlo[r1] = hpack_lo(v2, v3);
        } else if (nglob < 128) {
            int col = nglob - 64;
            size_t r0 = (size_t)(m0 + row_l) * DH + col;
            size_t r1 = (size_t)(m0 + row_l + 8) * DH + col;
            *(uint32_t*)&g_Khi[r0] = hpack_hi(v0, v1);
            *(uint32_t*)&g_Khi[r1] = hpack_hi(v2, v3);
        } else {
            int d = nglob - 128;
            sV[row_l * 68 + d]       = v0;
            sV[row_l * 68 + d + 1]   = v1;
            sV[(row_l + 8) * 68 + d]     = v2;
            sV[(row_l + 8) * 68 + d + 1] = v3;
        }
    }
    __syncthreads();

    // Transposed VT store: thread -> (d, 16-row m segment)
    {
        int d    = tid >> 2;
        int mseg = (tid & 3) * 16;
        int b    = m0 >> 11;
        int s0   = (m0 & 2047) + mseg;
        uint32_t hw[8];
        #pragma unroll
        for (int i = 0; i < 8; i++) {
            float c0 = sV[(mseg + 2 * i) * 68 + d];
            float c1 = sV[(mseg + 2 * i + 1) * 68 + d];
            hw[i] = hpack_hi(c0, c1);
        }
        size_t base = ((size_t)b * DH + d) * SEQ + s0;
        *(uint4*)&g_VThi[base]     = make_uint4(hw[0], hw[1], hw[2], hw[3]);
        *(uint4*)&g_VThi[base + 8] = make_uint4(hw[4], hw[5], hw[6], hw[7]);
    }
}

// ---------------------------------------------------------------------------
// Kernel 2: fused masked attention. Same tiles/registers as the 180.2us
// version, but k-tiles processed in PAIRS: one wait_group + one
// __syncthreads + one prefetch block per 128 k-rows (16 sync points
// instead of 32). Hazard ordering: wait -> barrier -> issue t+2,t+3
// (their ring slots were read last iteration, fenced by this barrier).
// gemm1 = (Qhi+Qlo)·Khi, gemm2 = P_fp16·Vhi.
// ---------------------------------------------------------------------------
#define SRB 144                          // smem row stride bytes (72 halves)
#define AT_QH 0                          // 64 x 144 = 9216
#define AT_QL 9216
#define AT_STAGE 18432                   // 4 stages x (KH 9216 + VH 9216)
#define AT_SMEM (AT_STAGE + 4 * 18432)   // 92160

__global__ __launch_bounds__(128) void attn_mma_kernel(
    const int* __restrict__ mask,
    float* __restrict__ out)
{
    extern __shared__ char sm[];
    const uint32_t sb = smem_u32(sm);
    const int tid = threadIdx.x;
    const int wid = tid >> 5;
    const int lid = tid & 31;
    const int g   = lid >> 2;
    const int tig = lid & 3;
    const int b   = blockIdx.y;
    const int q0  = blockIdx.x * 64;

    // stage issue helper: stage s covers k-tile s
    #define ISSUE_STAGE(s_) do {                                                   \
        int s = (s_);                                                              \
        _Pragma("unroll")                                                          \
        for (int u = 0; u < 8; u++) {                                              \
            int c = tid + u * 128;                                                 \
            int sel = c >> 9;                                                      \
            int cc = c & 511;                                                      \
            int row = cc >> 3, seg = cc & 7;                                       \
            uint32_t dst = sb + AT_STAGE + (s & 3) * 18432 + sel * 9216            \
                         + row * SRB + seg * 16;                                   \
            const __half* src = sel                                                \
                ? g_VThi + ((size_t)b * DH + row) * SEQ + s * 64 + seg * 8         \
                : g_Khi  + (size_t)(b * SEQ + s * 64 + row) * DH + seg * 8;        \
            cp16(dst, src);                                                        \
        }                                                                          \
    } while (0)

    // ---- prologue: Q tile (hi/lo) + stage 0 in group 0; stage 1 in group 1
    #pragma unroll
    for (int u = 0; u < 8; u++) {
        int c = tid + u * 128;            // 0..1023
        int half_ = c >> 9;
        int cc = c & 511;
        int row = cc >> 3, seg = cc & 7;
        uint32_t dst = sb + half_ * 9216 + row * SRB + seg * 16;
        const __half* src =
            (half_ ? g_Qlo : g_Qhi) + (size_t)(b * SEQ + q0 + row) * DH + seg * 8;
        cp16(dst, src);
    }
    ISSUE_STAGE(0);
    CP_COMMIT();
    ISSUE_STAGE(1);
    CP_COMMIT();

    float acc[8][4];
    #pragma unroll
    for (int j = 0; j < 8; j++)
        #pragma unroll
        for (int i = 0; i < 4; i++) acc[j][i] = 0.0f;
    float l0 = 0.0f, l1 = 0.0f;

    const int mrow = wid * 16;
    const float CEXP = 0.125f * 1.44269504f;
    const int* mr0 = mask + ((size_t)b * SEQ + q0 + mrow + g) * SEQ + 2 * tig;
    const int* mr1 = mr0 + 8 * SEQ;

    // ldmatrix per-lane address components
    const int rowA  = mrow + (lid & 7) + ((lid >> 3) & 1) * 8;
    const int byteA = (lid >> 4) * 16;
    const int rowB  = (lid & 7) + (lid >> 4) * 8;
    const int byteB = ((lid >> 3) & 1) * 16;
    const uint32_t aQH = sb + AT_QH + rowA * SRB + byteA;
    const uint32_t aQL = aQH + 9216;
    const uint32_t aBV = rowB * SRB + byteB;     // add stage base

    // per-64-tile compute block: mask load, gemm1, softmax, gemm2.
    // All temporaries scoped so register live ranges match the R7 structure.
    #define COMPUTE_TILE(ktv) do {                                                 \
        const int kt_ = (ktv);                                                     \
        int2 mv0[8], mv1[8];                                                       \
        _Pragma("unroll")                                                          \
        for (int j = 0; j < 8; j++) {                                              \
            mv0[j] = *(const int2*)(mr0 + kt_ * 64 + j * 8);                       \
            mv1[j] = *(const int2*)(mr1 + kt_ * 64 + j * 8);                       \
        }                                                                          \
        const uint32_t stg_ = sb + AT_STAGE + (kt_ & 3) * 18432;                   \
        const uint32_t aKH_ = stg_ + aBV;                                          \
        const uint32_t aVH_ = aKH_ + 9216;                                         \
        float s[8][4];                                                             \
        _Pragma("unroll")                                                          \
        for (int j = 0; j < 8; j++)                                                \
            { s[j][0] = 0.0f; s[j][1] = 0.0f; s[j][2] = 0.0f; s[j][3] = 0.0f; }    \
        _Pragma("unroll")                                                          \
        for (int ks = 0; ks < 4; ks++) {                                           \
            uint32_t ah[4], al[4];                                                 \
            ldsm4(ah, aQH + ks * 32);                                              \
            ldsm4(al, aQL + ks * 32);                                              \
            _Pragma("unroll")                                                      \
            for (int jp = 0; jp < 4; jp++) {                                       \
                uint32_t bh[4];                                                    \
                ldsm4(bh, aKH_ + jp * (16 * SRB) + ks * 32);                       \
                mma_f16(s[2 * jp],     ah, bh);                                    \
                mma_f16(s[2 * jp],     al, bh);                                    \
                mma_f16(s[2 * jp + 1], ah, bh + 2);                                \
                mma_f16(s[2 * jp + 1], al, bh + 2);                                \
            }                                                                      \
        }                                                                          \
        _Pragma("unroll")                                                          \
        for (int j = 0; j < 8; j++) {                                              \
            float p0 = (mv0[j].x == 1) ? 1.0f : fexp2(s[j][0] * CEXP);             \
            float p1 = (mv0[j].y == 1) ? 1.0f : fexp2(s[j][1] * CEXP);             \
            float p2 = (mv1[j].x == 1) ? 1.0f : fexp2(s[j][2] * CEXP);             \
            float p3 = (mv1[j].y == 1) ? 1.0f : fexp2(s[j][3] * CEXP);             \
            s[j][0] = p0; s[j][1] = p1; s[j][2] = p2; s[j][3] = p3;                \
            l0 += p0 + p1;                                                         \
            l1 += p2 + p3;                                                         \
        }                                                                          \
        _Pragma("unroll")                                                          \
        for (int k2 = 0; k2 < 4; k2++) {                                           \
            const float* pa = s[2 * k2];                                           \
            const float* pb = s[2 * k2 + 1];                                       \
            uint32_t ph[4];                                                        \
            ph[0] = hpack_hi(pa[0], pa[1]);                                        \
            ph[1] = hpack_hi(pa[2], pa[3]);                                        \
            ph[2] = hpack_hi(pb[0], pb[1]);                                        \
            ph[3] = hpack_hi(pb[2], pb[3]);                                        \
            _Pragma("unroll")                                                      \
            for (int jp = 0; jp < 4; jp++) {                                       \
                uint32_t vh[4];                                                    \
                ldsm4(vh, aVH_ + jp * (16 * SRB) + k2 * 32);                       \
                mma_f16(acc[2 * jp],     ph, vh);                                  \
                mma_f16(acc[2 * jp + 1], ph, vh + 2);                              \
            }                                                                      \
        }                                                                          \
    } while (0)

    #pragma unroll 1
    for (int kp = 0; kp < NKT / 2; kp++) {
        const int t0 = 2 * kp;
        // wait for tiles t0, t0+1 (issued last iteration, after its barrier)
        asm volatile("cp.async.wait_group 0;" ::: "memory");
        __syncthreads();
        // prefetch tiles t0+2, t0+3 — their ring slots were consumed in the
        // previous iteration, which the barrier above just fenced (WAR safe).
        if (t0 + 2 < NKT) {
            ISSUE_STAGE(t0 + 2);
            CP_COMMIT();
            ISSUE_STAGE(t0 + 3);
            CP_COMMIT();
        }
        COMPUTE_TILE(t0);
        COMPUTE_TILE(t0 + 1);
    }

    // ---- epilogue: reduce l across the 4 lanes sharing a row, divide, store
    l0 += __shfl_xor_sync(0xffffffffu, l0, 1);
    l0 += __shfl_xor_sync(0xffffffffu, l0, 2);
    l1 += __shfl_xor_sync(0xffffffffu, l1, 1);
    l1 += __shfl_xor_sync(0xffffffffu, l1, 2);
    float inv0 = 1.0f / l0, inv1 = 1.0f / l1;

    size_t r0 = (size_t)(b * SEQ + q0 + mrow + g) * DH;
    size_t r1 = r0 + 8 * DH;
    #pragma unroll
    for (int j2 = 0; j2 < 8; j2++) {
        int col = j2 * 8 + 2 * tig;
        *(float2*)&out[r0 + col] = make_float2(acc[j2][0] * inv0, acc[j2][1] * inv0);
        *(float2*)&out[r1 + col] = make_float2(acc[j2][2] * inv1, acc[j2][3] * inv1);
    }
    #undef COMPUTE_TILE
    #undef ISSUE_STAGE
}

// ---------------------------------------------------------------------------
extern "C" void kernel_launch(void* const* d_in, const int* in_sizes, int n_in,
                              void* d_out, int out_size)
{
    const float* x    = (const float*)d_in[0];
    const int*   mask = (const int*)d_in[1];
    const float* W    = (const float*)d_in[2];
    const float* bias = (const float*)d_in[3];
    float* out = (float*)d_out;

    (void)in_sizes; (void)n_in; (void)out_size;

    static int attr_set = 0;
    if (!attr_set) {
        cudaFuncSetAttribute(attn_mma_kernel,
                             cudaFuncAttributeMaxDynamicSharedMemorySize, AT_SMEM);
        attr_set = 1;
    }

    wconv_kernel<<<(192 * EMB) / 256, 256>>>(W);
    qkv_mma_kernel<<<NROWS / 64, 256>>>(x, bias);

    dim3 g2(SEQ / 64, BATCH);
    attn_mma_kernel<<<g2, 128, AT_SMEM>>>(mask, out);
}

// round 17
// speedup vs baseline: 1.3214x; 1.3214x over previous
#include <cuda_runtime.h>
#include <cuda_fp16.h>
#include <math.h>
#include <stdint.h>

#define BATCH 8
#define SEQ   2048
#define EMB   1024
#define DH    64
#define NROWS (BATCH * SEQ)   // 16384
#define NKT   (SEQ / 64)      // 32 k-tiles

// Pre-split fp16 operands produced by the QKV kernel.
__device__ __half g_Qhi[NROWS * DH];
__device__ __half g_Qlo[NROWS * DH];
__device__ __half g_Khi[NROWS * DH];
__device__ __half g_VThi[BATCH * DH * SEQ];  // [b][d][s]
__device__ __half g_WhiT[192 * EMB];          // [n][k]

// ---------------------------------------------------------------------------
// helpers
// ---------------------------------------------------------------------------
__device__ __forceinline__ void mma_f16(float* c, const uint32_t* a, const uint32_t* b) {
    asm volatile(
        "mma.sync.aligned.m16n8k16.row.col.f32.f16.f16.f32 "
        "{%0,%1,%2,%3}, {%4,%5,%6,%7}, {%8,%9}, {%0,%1,%2,%3};"
        : "+f"(c[0]), "+f"(c[1]), "+f"(c[2]), "+f"(c[3])
        : "r"(a[0]), "r"(a[1]), "r"(a[2]), "r"(a[3]), "r"(b[0]), "r"(b[1]));
}

__device__ __forceinline__ void ldsm4(uint32_t* r, uint32_t a) {
    asm volatile("ldmatrix.sync.aligned.m8n8.x4.shared.b16 {%0,%1,%2,%3}, [%4];"
        : "=r"(r[0]), "=r"(r[1]), "=r"(r[2]), "=r"(r[3]) : "r"(a));
}

__device__ __forceinline__ uint32_t smem_u32(const void* p) {
    uint32_t a;
    asm("{ .reg .u64 t; cvta.to.shared.u64 t, %1; cvt.u32.u64 %0, t; }"
        : "=r"(a) : "l"(p));
    return a;
}

__device__ __forceinline__ void cp16(uint32_t dst, const void* src) {
    asm volatile("cp.async.cg.shared.global [%0], [%1], 16;" :: "r"(dst), "l"(src));
}
#define CP_COMMIT() asm volatile("cp.async.commit_group;" ::: "memory")

// Fast 2^t on the FMA pipe (abs err ~2.4e-6 for |t| <= ~12).
__device__ __forceinline__ float fexp2(float t) {
    float z = t + 12582912.0f;
    float f = t - (z - 12582912.0f);
    int   e = __float_as_int(z) << 23;
    float p = 0.0013333558f;
    p = fmaf(p, f, 0.0096181291f);
    p = fmaf(p, f, 0.0555041087f);
    p = fmaf(p, f, 0.2402265070f);
    p = fmaf(p, f, 0.6931471806f);
    p = fmaf(p, f, 1.0f);
    return __int_as_float(__float_as_int(p) + e);
}

__device__ __forceinline__ uint32_t hpack_hi(float a, float b) {
    __half2 h = __floats2half2_rn(a, b);
    return *(uint32_t*)&h;
}
__device__ __forceinline__ uint32_t hpack_lo(float a, float b) {
    __half ha = __float2half_rn(a), hb = __float2half_rn(b);
    __half2 l = __halves2half2(__float2half_rn(a - __half2float(ha)),
                               __float2half_rn(b - __half2float(hb)));
    return *(uint32_t*)&l;
}

// ---------------------------------------------------------------------------
// Kernel 0: W [1024,192] fp32 -> transposed hi fp16 [192][1024]
// ---------------------------------------------------------------------------
__global__ void wconv_kernel(const float* __restrict__ W) {
    int idx = blockIdx.x * 256 + threadIdx.x;
    int k = idx & 1023;
    int n = idx >> 10;
    g_WhiT[(size_t)n * EMB + k] = __float2half_rn(W[(size_t)k * 192 + n]);
}

// ---------------------------------------------------------------------------
// Kernel 1: QKV projection (mma.sync, x split hi/lo, W hi only: 2-term).
// Byte-identical to the proven 180.2us R12 version.
// ---------------------------------------------------------------------------
#define ASTR 40
#define QSM_AHI 0
#define QSM_ALO 5120
#define QSM_BHI 10240
#define QSM_TOT 25600

__global__ __launch_bounds__(256) void qkv_mma_kernel(
    const float* __restrict__ x,
    const float* __restrict__ bias)
{
    __shared__ char qsm[QSM_TOT];
    __half* sAhi = (__half*)(qsm + QSM_AHI);
    __half* sAlo = (__half*)(qsm + QSM_ALO);
    __half* sBhi = (__half*)(qsm + QSM_BHI);

    const int tid = threadIdx.x;
    const int lid = tid & 31;
    const int wid = tid >> 5;
    const int g   = lid >> 2;
    const int tig = lid & 3;
    const int warp_m = wid & 3;
    const int warp_n = wid >> 2;
    const int m0 = blockIdx.x * 64;

    float acc[12][4];
    #pragma unroll
    for (int j = 0; j < 12; j++)
        #pragma unroll
        for (int i = 0; i < 4; i++) acc[j][i] = 0.0f;

    for (int k0 = 0; k0 < EMB; k0 += 32) {
        __syncthreads();
        #pragma unroll
        for (int u = 0; u < 2; u++) {
            int id  = tid + u * 256;
            int row = id >> 3;
            int c4  = id & 7;
            float4 v = *(const float4*)&x[(size_t)(m0 + row) * EMB + k0 + c4 * 4];
            int e = row * ASTR + c4 * 4;
            *(uint32_t*)&sAhi[e]     = hpack_hi(v.x, v.y);
            *(uint32_t*)&sAhi[e + 2] = hpack_hi(v.z, v.w);
            *(uint32_t*)&sAlo[e]     = hpack_lo(v.x, v.y);
            *(uint32_t*)&sAlo[e + 2] = hpack_lo(v.z, v.w);
        }
        #pragma unroll
        for (int u = 0; u < 6; u++) {
            int id  = tid + u * 256;
            int row = id >> 3;
            int c   = id & 7;
            uint2 vh = *(const uint2*)&g_WhiT[(size_t)row * EMB + k0 + c * 4];
            *(uint2*)&sBhi[row * ASTR + c * 4] = vh;
        }
        __syncthreads();

        #pragma unroll
        for (int ks = 0; ks < 2; ks++) {
            const int kb = ks * 16;
            const int ra = warp_m * 16 + g;
            uint32_t ah[4], al[4];
            ah[0] = *(const uint32_t*)&sAhi[ra * ASTR + kb + 2 * tig];
            ah[1] = *(const uint32_t*)&sAhi[(ra + 8) * ASTR + kb + 2 * tig];
            ah[2] = *(const uint32_t*)&sAhi[ra * ASTR + kb + 8 + 2 * tig];
            ah[3] = *(const uint32_t*)&sAhi[(ra + 8) * ASTR + kb + 8 + 2 * tig];
            al[0] = *(const uint32_t*)&sAlo[ra * ASTR + kb + 2 * tig];
            al[1] = *(const uint32_t*)&sAlo[(ra + 8) * ASTR + kb + 2 * tig];
            al[2] = *(const uint32_t*)&sAlo[ra * ASTR + kb + 8 + 2 * tig];
            al[3] = *(const uint32_t*)&sAlo[(ra + 8) * ASTR + kb + 8 + 2 * tig];

            #pragma unroll
            for (int j = 0; j < 12; j++) {
                const int nb = warp_n * 96 + j * 8 + g;
                uint32_t bh[2];
                bh[0] = *(const uint32_t*)&sBhi[nb * ASTR + kb + 2 * tig];
                bh[1] = *(const uint32_t*)&sBhi[nb * ASTR + kb + 8 + 2 * tig];
                mma_f16(acc[j], ah, bh);
                mma_f16(acc[j], al, bh);
            }
        }
    }

    __syncthreads();   // done with A/B tiles; reuse smem for V staging
    float* sV = (float*)qsm;       // [64][68] fp32 = 17408 B
    const int row_l = warp_m * 16 + g;

    #pragma unroll
    for (int j = 0; j < 12; j++) {
        int nglob = warp_n * 96 + j * 8 + 2 * tig;
        float b0 = bias[nglob], b1 = bias[nglob + 1];
        float v0 = acc[j][0] + b0, v1 = acc[j][1] + b1;
        float v2 = acc[j][2] + b0, v3 = acc[j][3] + b1;
        if (nglob < 64) {
            size_t r0 = (size_t)(m0 + row_l) * DH + nglob;
            size_t r1 = (size_t)(m0 + row_l + 8) * DH + nglob;
            *(uint32_t*)&g_Qhi[r0] = hpack_hi(v0, v1);
            *(uint32_t*)&g_Qlo[r0] = hpack_lo(v0, v1);
            *(uint32_t*)&g_Qhi[r1] = hpack_hi(v2, v3);
            *(uint32_t*)&g_Qlo[r1] = hpack_lo(v2, v3);
        } else if (nglob < 128) {
            int col = nglob - 64;
            size_t r0 = (size_t)(m0 + row_l) * DH + col;
            size_t r1 = (size_t)(m0 + row_l + 8) * DH + col;
            *(uint32_t*)&g_Khi[r0] = hpack_hi(v0, v1);
            *(uint32_t*)&g_Khi[r1] = hpack_hi(v2, v3);
        } else {
            int d = nglob - 128;
            sV[row_l * 68 + d]       = v0;
            sV[row_l * 68 + d + 1]   = v1;
            sV[(row_l + 8) * 68 + d]     = v2;
            sV[(row_l + 8) * 68 + d + 1] = v3;
        }
    }
    __syncthreads();

    // Transposed VT store: thread -> (d, 16-row m segment)
    {
        int d    = tid >> 2;
        int mseg = (tid & 3) * 16;
        int b    = m0 >> 11;
        int s0   = (m0 & 2047) + mseg;
        uint32_t hw[8];
        #pragma unroll
        for (int i = 0; i < 8; i++) {
            float c0 = sV[(mseg + 2 * i) * 68 + d];
            float c1 = sV[(mseg + 2 * i + 1) * 68 + d];
            hw[i] = hpack_hi(c0, c1);
        }
        size_t base = ((size_t)b * DH + d) * SEQ + s0;
        *(uint4*)&g_VThi[base]     = make_uint4(hw[0], hw[1], hw[2], hw[3]);
        *(uint4*)&g_VThi[base + 8] = make_uint4(hw[4], hw[5], hw[6], hw[7]);
    }
}

// ---------------------------------------------------------------------------
// Kernel 2: fused masked attention, SPLIT-K warp layout.
// 256 threads = 8 warps: warp-group hf = wid>>2 handles k-columns
// [32*hf, 32*hf+32) of each 64-wide k-tile; warp_m = wid&3 owns q-rows
// warp_m*16..+15. Same smem/pipeline as the 180.2us version (4-stage ring,
// issue kt+2 -> wait_group 2 -> one sync). Partial acc/l reduced across
// halves via smem at the end. 16 warps/SM (4/SMSP) vs previous 8.
// ---------------------------------------------------------------------------
#define SRB 144                          // smem row stride bytes (72 halves)
#define AT_QH 0                          // 64 x 144 = 9216
#define AT_QL 9216
#define AT_STAGE 18432                   // 4 stages x (KH 9216 + VH 9216)
#define AT_SMEM (AT_STAGE + 4 * 18432)   // 92160

__global__ __launch_bounds__(256, 2) void attn_mma_kernel(
    const int* __restrict__ mask,
    float* __restrict__ out)
{
    extern __shared__ char sm[];
    const uint32_t sb = smem_u32(sm);
    const int tid = threadIdx.x;
    const int wid = tid >> 5;
    const int lid = tid & 31;
    const int g   = lid >> 2;
    const int tig = lid & 3;
    const int hf  = wid >> 2;           // 0/1: which 32 k-cols of the tile
    const int warp_m = wid & 3;
    const int b   = blockIdx.y;
    const int q0  = blockIdx.x * 64;

    // stage issue helper: stage s covers k-tile s (1024 cp16 units, 256 thr)
    #define ISSUE_STAGE(s_) do {                                                   \
        int s = (s_);                                                              \
        _Pragma("unroll")                                                          \
        for (int u = 0; u < 4; u++) {                                              \
            int c = tid + u * 256;                                                 \
            int sel = c >> 9;                                                      \
            int cc = c & 511;                                                      \
            int row = cc >> 3, seg = cc & 7;                                       \
            uint32_t dst = sb + AT_STAGE + (s & 3) * 18432 + sel * 9216            \
                         + row * SRB + seg * 16;                                   \
            const __half* src = sel                                                \
                ? g_VThi + ((size_t)b * DH + row) * SEQ + s * 64 + seg * 8         \
                : g_Khi  + (size_t)(b * SEQ + s * 64 + row) * DH + seg * 8;        \
            cp16(dst, src);                                                        \
        }                                                                          \
    } while (0)

    // ---- prologue: Q tile (hi/lo) + stage 0 in group 0; stage 1 in group 1
    #pragma unroll
    for (int u = 0; u < 4; u++) {
        int c = tid + u * 256;            // 0..1023
        int half_ = c >> 9;
        int cc = c & 511;
        int row = cc >> 3, seg = cc & 7;
        uint32_t dst = sb + half_ * 9216 + row * SRB + seg * 16;
        const __half* src =
            (half_ ? g_Qlo : g_Qhi) + (size_t)(b * SEQ + q0 + row) * DH + seg * 8;
        cp16(dst, src);
    }
    ISSUE_STAGE(0);
    CP_COMMIT();
    ISSUE_STAGE(1);
    CP_COMMIT();

    float acc[8][4];
    #pragma unroll
    for (int j = 0; j < 8; j++)
        #pragma unroll
        for (int i = 0; i < 4; i++) acc[j][i] = 0.0f;
    float l0 = 0.0f, l1 = 0.0f;

    const int mrow = warp_m * 16;
    const float CEXP = 0.125f * 1.44269504f;
    // mask base includes this warp-group's 32-col offset
    const int* mr0 = mask + ((size_t)b * SEQ + q0 + mrow + g) * SEQ + hf * 32 + 2 * tig;
    const int* mr1 = mr0 + 8 * SEQ;

    // ldmatrix per-lane address components
    const int rowA  = mrow + (lid & 7) + ((lid >> 3) & 1) * 8;
    const int byteA = (lid >> 4) * 16;
    const int rowB  = (lid & 7) + (lid >> 4) * 8;
    const int byteB = ((lid >> 3) & 1) * 16;
    const uint32_t aQH = sb + AT_QH + rowA * SRB + byteA;
    const uint32_t aQL = aQH + 9216;
    const uint32_t aBV = rowB * SRB + byteB;     // add stage base

    #pragma unroll 1
    for (int kt = 0; kt < NKT; kt++) {
        if (kt + 2 < NKT) {
            ISSUE_STAGE(kt + 2);
            CP_COMMIT();
            asm volatile("cp.async.wait_group 2;" ::: "memory");
        } else if (kt + 1 < NKT) {
            asm volatile("cp.async.wait_group 1;" ::: "memory");
        } else {
            asm volatile("cp.async.wait_group 0;" ::: "memory");
        }
        __syncthreads();

        // mask prefetch for this warp-group's 32 cols
        int2 mv0[4], mv1[4];
        #pragma unroll
        for (int j = 0; j < 4; j++) {
            mv0[j] = *(const int2*)(mr0 + kt * 64 + j * 8);
            mv1[j] = *(const int2*)(mr1 + kt * 64 + j * 8);
        }

        const uint32_t stg = sb + AT_STAGE + (kt & 3) * 18432;
        const uint32_t aKH = stg + aBV;
        const uint32_t aVH = aKH + 9216;

        // ---- gemm1: S = (Qhi + Qlo) · Khi over this half's 32 K-rows
        float s[4][4];
        #pragma unroll
        for (int j = 0; j < 4; j++)
            #pragma unroll
            for (int i = 0; i < 4; i++) s[j][i] = 0.0f;

        #pragma unroll
        for (int ks = 0; ks < 4; ks++) {
            uint32_t ah[4], al[4];
            ldsm4(ah, aQH + ks * 32);
            ldsm4(al, aQL + ks * 32);
            #pragma unroll
            for (int p = 0; p < 2; p++) {
                uint32_t bh[4];
                ldsm4(bh, aKH + (hf * 2 + p) * (16 * SRB) + ks * 32);
                mma_f16(s[2 * p],     ah, bh);
                mma_f16(s[2 * p],     al, bh);
                mma_f16(s[2 * p + 1], ah, bh + 2);
                mma_f16(s[2 * p + 1], al, bh + 2);
            }
        }

        // ---- softmax piece (this half's 32 cols)
        #pragma unroll
        for (int j = 0; j < 4; j++) {
            float p0 = (mv0[j].x == 1) ? 1.0f : fexp2(s[j][0] * CEXP);
            float p1 = (mv0[j].y == 1) ? 1.0f : fexp2(s[j][1] * CEXP);
            float p2 = (mv1[j].x == 1) ? 1.0f : fexp2(s[j][2] * CEXP);
            float p3 = (mv1[j].y == 1) ? 1.0f : fexp2(s[j][3] * CEXP);
            s[j][0] = p0; s[j][1] = p1; s[j][2] = p2; s[j][3] = p3;
            l0 += p0 + p1;
            l1 += p2 + p3;
        }

        // ---- gemm2: acc += P(half) · V(half k-slices), full d width
        #pragma unroll
        for (int k2l = 0; k2l < 2; k2l++) {
            const float* pa = s[2 * k2l];
            const float* pb = s[2 * k2l + 1];
            uint32_t ph[4];
            ph[0] = hpack_hi(pa[0], pa[1]);
            ph[1] = hpack_hi(pa[2], pa[3]);
            ph[2] = hpack_hi(pb[0], pb[1]);
            ph[3] = hpack_hi(pb[2], pb[3]);
            const int k2g = hf * 2 + k2l;
            #pragma unroll
            for (int jp = 0; jp < 4; jp++) {
                uint32_t vh[4];
                ldsm4(vh, aVH + jp * (16 * SRB) + k2g * 32);
                mma_f16(acc[2 * jp],     ph, vh);
                mma_f16(acc[2 * jp + 1], ph, vh + 2);
            }
        }
        // no trailing sync: 4-stage ring + top-of-loop sync covers WAR
    }

    // ---- epilogue: reduce l over tig lanes, then across halves via smem
    l0 += __shfl_xor_sync(0xffffffffu, l0, 1);
    l0 += __shfl_xor_sync(0xffffffffu, l0, 2);
    l1 += __shfl_xor_sync(0xffffffffu, l1, 1);
    l1 += __shfl_xor_sync(0xffffffffu, l1, 2);

    __syncthreads();   // all stage reads done; reuse stage smem for reduction
    float* red = (float*)(sm + AT_STAGE);
    const int slot = warp_m * 32 + lid;          // 0..127, same for both halves
    if (hf == 1) {
        float* pp = red + slot * 35;             // stride 35: conflict-free
        #pragma unroll
        for (int j = 0; j < 8; j++) {
            pp[j * 4 + 0] = acc[j][0];
            pp[j * 4 + 1] = acc[j][1];
            pp[j * 4 + 2] = acc[j][2];
            pp[j * 4 + 3] = acc[j][3];
        }
        pp[32] = l0;
        pp[33] = l1;
    }
    __syncthreads();
    if (hf == 0) {
        const float* pp = red + slot * 35;
        float l0t = l0 + pp[32];
        float l1t = l1 + pp[33];
        float inv0 = 1.0f / l0t, inv1 = 1.0f / l1t;
        size_t r0 = (size_t)(b * SEQ + q0 + mrow + g) * DH;
        size_t r1 = r0 + 8 * DH;
        #pragma unroll
        for (int j2 = 0; j2 < 8; j2++) {
            int col = j2 * 8 + 2 * tig;
            float a0 = (acc[j2][0] + pp[j2 * 4 + 0]) * inv0;
            float a1 = (acc[j2][1] + pp[j2 * 4 + 1]) * inv0;
            float a2 = (acc[j2][2] + pp[j2 * 4 + 2]) * inv1;
            float a3 = (acc[j2][3] + pp[j2 * 4 + 3]) * inv1;
            *(float2*)&out[r0 + col] = make_float2(a0, a1);
            *(float2*)&out[r1 + col] = make_float2(a2, a3);
        }
    }
    #undef ISSUE_STAGE
}

// ---------------------------------------------------------------------------
extern "C" void kernel_launch(void* const* d_in, const int* in_sizes, int n_in,
                              void* d_out, int out_size)
{
    const float* x    = (const float*)d_in[0];
    const int*   mask = (const int*)d_in[1];
    const float* W    = (const float*)d_in[2];
    const float* bias = (const float*)d_in[3];
    float* out = (float*)d_out;

    (void)in_sizes; (void)n_in; (void)out_size;

    static int attr_set = 0;
    if (!attr_set) {
        cudaFuncSetAttribute(attn_mma_kernel,
                             cudaFuncAttributeMaxDynamicSharedMemorySize, AT_SMEM);
        attr_set = 1;
    }

    wconv_kernel<<<(192 * EMB) / 256, 256>>>(W);
    qkv_mma_kernel<<<NROWS / 64, 256>>>(x, bias);

    dim3 g2(SEQ / 64, BATCH);
    attn_mma_kernel<<<g2, 256, AT_SMEM>>>(mask, out);
}